// round 15
// baseline (speedup 1.0000x reference)
#include <cuda_runtime.h>
#include <cuda_fp16.h>
#include <math.h>
#include <stdint.h>

// Problem constants
#define Bb   16
#define NPp  512
#define Nn   1024
#define Cc   1024
#define Hh   16
#define HDd  64
#define C3   3072
#define HIDh 4096
#define Mtok 8192   // B*NP

// ---------------- scratch (device globals) ----------------
__device__ __half g_h  [(size_t)Mtok * Cc];          // LN out (half)
__device__ __half g_qkv[(size_t)Mtok * C3];          // QKV (half)
__device__ __half g_kf [(size_t)Bb * Hh * Nn * HDd]; // K full (half)
__device__ __half g_vf [(size_t)Bb * Hh * Nn * HDd]; // V full (half)
__device__ __half g_o  [(size_t)Mtok * Cc];          // attention out (half)
__device__ float  g_x1 [(size_t)Mtok * Cc];          // x + proj (float)
__device__ __half g_hid[(size_t)Mtok * HIDh];        // MLP hidden (half)
__device__ int    g_p2t[Bb * Nn];
// half, transposed [N][K] weights
__device__ __half g_wq [(size_t)C3 * Cc];
__device__ __half g_wp [(size_t)Cc * Cc];
__device__ __half g_w1 [(size_t)HIDh * Cc];
__device__ __half g_w2 [(size_t)Cc * HIDh];

// ---------------- helpers ----------------
__device__ __forceinline__ void mma_f16(float c[4], const uint32_t a[4], const uint32_t b[2]) {
    asm volatile(
        "mma.sync.aligned.m16n8k16.row.col.f32.f16.f16.f32 "
        "{%0,%1,%2,%3}, {%4,%5,%6,%7}, {%8,%9}, {%0,%1,%2,%3};"
        : "+f"(c[0]), "+f"(c[1]), "+f"(c[2]), "+f"(c[3])
        : "r"(a[0]), "r"(a[1]), "r"(a[2]), "r"(a[3]), "r"(b[0]), "r"(b[1]));
}
__device__ __forceinline__ uint32_t packh2(float a, float b) {
    __half2 h = __floats2half2_rn(a, b);
    return *reinterpret_cast<uint32_t*>(&h);
}
__device__ __forceinline__ void cp16(uint32_t saddr, const void* g) {
    asm volatile("cp.async.cg.shared.global [%0], [%1], 16;" :: "r"(saddr), "l"(g));
}
#define CP_COMMIT() asm volatile("cp.async.commit_group;")
#define CP_WAIT(n)  asm volatile("cp.async.wait_group %0;" :: "n"(n))

// ---------------- weight pre-round+transpose: float [K][N] -> half [N][K] ----------------
__global__ void wtrans_kernel(const float* __restrict__ wq, const float* __restrict__ wp,
                              const float* __restrict__ w1, const float* __restrict__ w2)
{
    __shared__ __half tile[32][33];
    int bid = blockIdx.x;
    const float* src; __half* dst; int K_, N_, tk, tn;
    if (bid < 3072)      { src = wq; dst = g_wq; K_ = Cc;   N_ = C3;   int id = bid;        tk = id / 96;  tn = id % 96; }
    else if (bid < 4096) { src = wp; dst = g_wp; K_ = Cc;   N_ = Cc;   int id = bid - 3072; tk = id / 32;  tn = id % 32; }
    else if (bid < 8192) { src = w1; dst = g_w1; K_ = Cc;   N_ = HIDh; int id = bid - 4096; tk = id / 128; tn = id % 128; }
    else                 { src = w2; dst = g_w2; K_ = HIDh; N_ = Cc;   int id = bid - 8192; tk = id / 32;  tn = id % 32; }
    int k0 = tk * 32, n0 = tn * 32;
    int t = threadIdx.x;
    #pragma unroll
    for (int it = 0; it < 4; it++) {
        int id = t + it * 256;
        int kk = id >> 5, nn = id & 31;
        tile[kk][nn] = __float2half_rn(src[(size_t)(k0 + kk) * N_ + n0 + nn]);
    }
    __syncthreads();
    #pragma unroll
    for (int it = 0; it < 4; it++) {
        int id = t + it * 256;
        int nn = id >> 5, kk = id & 31;
        dst[(size_t)(n0 + nn) * K_ + k0 + kk] = tile[kk][nn];
    }
}

// ---------------- fp16 mma.sync GEMM, cp.async 3-stage, BK=64 ----------------
// C = act(A @ B^T + bias) + resid ; A: half [M][K], B: half [N][K].
// BM=128, BN=128, BK=64; 256 thr = 8 warps, warp tile 64x32. 2 blocks/SM.
template<bool OUT_HALF, bool GELU_ACT, bool HAS_RES>
__global__ void __launch_bounds__(256) mma_gemm(
    const __half* __restrict__ A, const __half* __restrict__ Bm, void* __restrict__ Cm,
    int K, int lda, int ldb, int ldc,
    const float* __restrict__ bias, const float* __restrict__ resid)
{
    const int AW = 36;                              // row stride in words (72 halves)
    const int AWORDS = 128 * AW;                    // per matrix per stage
    const int STW = 2 * AWORDS;                     // 9216 words per stage

    extern __shared__ float sm[];

    int t = threadIdx.x, lane = t & 31, warp = t >> 5;
    int g = lane >> 2, tg = lane & 3;
    int wm = (warp >> 2) * 64, wn = (warp & 3) * 32;
    int m0 = blockIdx.y * 128, n0 = blockIdx.x * 128;

    const __half* Ab = A + (size_t)m0 * lda;
    const __half* Bb_ = Bm + (size_t)n0 * ldb;

    float acc[4][4][4];
    #pragma unroll
    for (int i = 0; i < 4; i++)
        #pragma unroll
        for (int j = 0; j < 4; j++)
            #pragma unroll
            for (int l = 0; l < 4; l++) acc[i][j][l] = 0.f;

    auto issue = [&](int kt, int st) {
        float* As = sm + st * STW;
        float* Bs = As + AWORDS;
        const __half* Ag = Ab + kt * 64;
        const __half* Bg = Bb_ + kt * 64;
        #pragma unroll
        for (int it = 0; it < 4; it++) {            // A: 128 rows x 64 halves = 1024 chunks
            int c = t + it * 256;
            int r = c >> 3, c8 = (c & 7) * 8;
            cp16((uint32_t)__cvta_generic_to_shared(As + r * AW + c8 / 2),
                 Ag + (size_t)r * lda + c8);
        }
        #pragma unroll
        for (int it = 0; it < 4; it++) {            // B: same shape
            int c = t + it * 256;
            int r = c >> 3, c8 = (c & 7) * 8;
            cp16((uint32_t)__cvta_generic_to_shared(Bs + r * AW + c8 / 2),
                 Bg + (size_t)r * ldb + c8);
        }
        CP_COMMIT();
    };

    auto compute = [&](int st) {
        const uint32_t* As = reinterpret_cast<const uint32_t*>(sm + st * STW);
        const uint32_t* Bs = As + AWORDS;
        #pragma unroll
        for (int ks = 0; ks < 4; ks++) {            // 4 k16 steps
            int k0 = ks * 8;                        // word offset
            uint32_t af[4][4], bf[4][2];
            #pragma unroll
            for (int mt = 0; mt < 4; mt++) {
                int r = wm + mt * 16 + g;
                af[mt][0] = As[r * AW + k0 + tg];
                af[mt][1] = As[(r + 8) * AW + k0 + tg];
                af[mt][2] = As[r * AW + k0 + tg + 4];
                af[mt][3] = As[(r + 8) * AW + k0 + tg + 4];
            }
            #pragma unroll
            for (int nt = 0; nt < 4; nt++) {
                int c = wn + nt * 8 + g;
                bf[nt][0] = Bs[c * AW + k0 + tg];
                bf[nt][1] = Bs[c * AW + k0 + tg + 4];
            }
            #pragma unroll
            for (int mt = 0; mt < 4; mt++)
                #pragma unroll
                for (int nt = 0; nt < 4; nt++)
                    mma_f16(acc[mt][nt], af[mt], bf[nt]);
        }
    };

    const int KT = K / 64;
    issue(0, 0);
    issue(1, 1);

    for (int kt = 0; kt < KT; kt++) {
        if (kt + 1 < KT) { CP_WAIT(1); } else { CP_WAIT(0); }
        __syncthreads();
        compute(kt % 3);
        if (kt + 2 < KT) issue(kt + 2, (kt + 2) % 3);
    }

    // ---- epilogue ----
    #pragma unroll
    for (int mt = 0; mt < 4; mt++) {
        int r0 = m0 + wm + mt * 16 + g;
        #pragma unroll
        for (int nt = 0; nt < 4; nt++) {
            int c = n0 + wn + nt * 8 + 2 * tg;
            #pragma unroll
            for (int half_ = 0; half_ < 2; half_++) {
                int r = r0 + half_ * 8;
                float v0 = acc[mt][nt][half_ * 2 + 0];
                float v1 = acc[mt][nt][half_ * 2 + 1];
                v0 += bias[c]; v1 += bias[c + 1];
                if (GELU_ACT) {
                    v0 = 0.5f * v0 * (1.0f + erff(v0 * 0.70710678118654752f));
                    v1 = 0.5f * v1 * (1.0f + erff(v1 * 0.70710678118654752f));
                }
                if (HAS_RES) {
                    float2 rv = *reinterpret_cast<const float2*>(
                        resid + (size_t)r * ldc + c);
                    v0 += rv.x; v1 += rv.y;
                }
                if (OUT_HALF) {
                    __half2 hv = __floats2half2_rn(v0, v1);
                    *reinterpret_cast<__half2*>((__half*)Cm + (size_t)r * ldc + c) = hv;
                } else {
                    float2 ov; ov.x = v0; ov.y = v1;
                    *reinterpret_cast<float2*>((float*)Cm + (size_t)r * ldc + c) = ov;
                }
            }
        }
    }
}

// ---------------- fused flash attention, fp16 mma, half Q ----------------
__global__ void __launch_bounds__(256) flash_kernel(
    const __half* __restrict__ qkv, const __half* __restrict__ kf,
    const __half* __restrict__ vf, __half* __restrict__ o)
{
    extern __shared__ float fsm[];
    const int KVH = 72;                      // row stride (halves)
    const int KVHALVES = 64 * KVH;

    __half* hsm = reinterpret_cast<__half*>(fsm);

    int t = threadIdx.x, lane = t & 31, w = t >> 5;
    int g = lane >> 2, tg = lane & 3;
    int bh = blockIdx.y, b = bh >> 4, h = bh & 15;
    int q0 = blockIdx.x * 128;

    // ---- Q (half) -> smem ----
    const __half* Qg = qkv + ((size_t)(b * NPp + q0)) * C3 + h * HDd;
    #pragma unroll
    for (int it = 0; it < 4; it++) {
        int id = t + it * 256;               // 1024 chunks of 8 halves
        int r = id >> 3, c8 = (id & 7) * 8;
        uint4 v = *reinterpret_cast<const uint4*>(Qg + (size_t)r * C3 + c8);
        *reinterpret_cast<uint4*>(hsm + r * KVH + c8) = v;
    }
    __syncthreads();

    // ---- Q fragments: scaled by 0.125 via hmul2 ----
    uint32_t qf[4][4];
    {
        const uint32_t* Q32 = reinterpret_cast<const uint32_t*>(hsm);
        const __half2 sc = __floats2half2_rn(0.125f, 0.125f);
        int r0 = w * 16 + g;
        #pragma unroll
        for (int kc = 0; kc < 4; kc++) {
            int wc = kc * 8 + tg;            // word col
            #pragma unroll
            for (int i = 0; i < 4; i++) {
                int rr = (i & 1) ? r0 + 8 : r0;
                int cc = wc + ((i >> 1) ? 4 : 0);
                uint32_t u = Q32[rr * (KVH / 2) + cc];
                __half2 hv = __hmul2(*reinterpret_cast<__half2*>(&u), sc);
                qf[kc][i] = *reinterpret_cast<uint32_t*>(&hv);
            }
        }
    }
    __syncthreads();

    const __half* Kg = kf + (size_t)bh * Nn * HDd;
    const __half* Vg = vf + (size_t)bh * Nn * HDd;

    auto issue_tile = [&](int j, int buf) {
        __half* Ks = hsm + buf * (2 * KVHALVES);
        __half* Vs = Ks + KVHALVES;
        const __half* kg = Kg + (size_t)j * 64 * HDd;
        const __half* vg = Vg + (size_t)j * 64 * HDd;
        #pragma unroll
        for (int it = 0; it < 2; it++) {
            int id = t + it * 256;
            int r = id >> 3, c8 = (id & 7) * 8;
            cp16((uint32_t)__cvta_generic_to_shared(Ks + r * KVH + c8), kg + r * HDd + c8);
            cp16((uint32_t)__cvta_generic_to_shared(Vs + r * KVH + c8), vg + r * HDd + c8);
        }
    };

    float m_r[2] = {-1e30f, -1e30f};
    float l_r[2] = {0.f, 0.f};
    float o_acc[8][4];
    #pragma unroll
    for (int i = 0; i < 8; i++)
        #pragma unroll
        for (int j = 0; j < 4; j++) o_acc[i][j] = 0.f;

    const unsigned FULL = 0xffffffffu;

    issue_tile(0, 0);
    CP_COMMIT();

    for (int j = 0; j < Nn / 64; j++) {
        int buf = j & 1;
        if (j + 1 < Nn / 64) { issue_tile(j + 1, buf ^ 1); CP_COMMIT(); CP_WAIT(1); }
        else                 { CP_WAIT(0); }
        __syncthreads();

        const __half* Ks = hsm + buf * (2 * KVHALVES);
        const __half* Vs = Ks + KVHALVES;
        const uint32_t* K32 = reinterpret_cast<const uint32_t*>(Ks);

        float s[8][4];
        #pragma unroll
        for (int nt = 0; nt < 8; nt++)
            #pragma unroll
            for (int i = 0; i < 4; i++) s[nt][i] = 0.f;
        #pragma unroll
        for (int kc = 0; kc < 4; kc++) {
            #pragma unroll
            for (int nt = 0; nt < 8; nt++) {
                int rowbase = (nt * 8 + g) * (KVH / 2) + kc * 8 + tg;
                uint32_t bb[2];
                bb[0] = K32[rowbase];
                bb[1] = K32[rowbase + 4];
                mma_f16(s[nt], qf[kc], bb);
            }
        }

        float mn0 = m_r[0], mn1 = m_r[1];
        #pragma unroll
        for (int nt = 0; nt < 8; nt++) {
            mn0 = fmaxf(mn0, fmaxf(s[nt][0], s[nt][1]));
            mn1 = fmaxf(mn1, fmaxf(s[nt][2], s[nt][3]));
        }
        mn0 = fmaxf(mn0, __shfl_xor_sync(FULL, mn0, 1));
        mn0 = fmaxf(mn0, __shfl_xor_sync(FULL, mn0, 2));
        mn1 = fmaxf(mn1, __shfl_xor_sync(FULL, mn1, 1));
        mn1 = fmaxf(mn1, __shfl_xor_sync(FULL, mn1, 2));
        float c0 = __expf(m_r[0] - mn0);
        float c1 = __expf(m_r[1] - mn1);
        m_r[0] = mn0; m_r[1] = mn1;

        float pf_[8][4];
        float rs0 = 0.f, rs1 = 0.f;
        #pragma unroll
        for (int nt = 0; nt < 8; nt++) {
            pf_[nt][0] = __expf(s[nt][0] - mn0);
            pf_[nt][1] = __expf(s[nt][1] - mn0);
            pf_[nt][2] = __expf(s[nt][2] - mn1);
            pf_[nt][3] = __expf(s[nt][3] - mn1);
            rs0 += pf_[nt][0] + pf_[nt][1];
            rs1 += pf_[nt][2] + pf_[nt][3];
        }
        rs0 += __shfl_xor_sync(FULL, rs0, 1); rs0 += __shfl_xor_sync(FULL, rs0, 2);
        rs1 += __shfl_xor_sync(FULL, rs1, 1); rs1 += __shfl_xor_sync(FULL, rs1, 2);
        l_r[0] = l_r[0] * c0 + rs0;
        l_r[1] = l_r[1] * c1 + rs1;
        #pragma unroll
        for (int nt = 0; nt < 8; nt++) {
            o_acc[nt][0] *= c0; o_acc[nt][1] *= c0;
            o_acc[nt][2] *= c1; o_acc[nt][3] *= c1;
        }

        #pragma unroll
        for (int kc = 0; kc < 4; kc++) {
            uint32_t af[4];
            af[0] = packh2(pf_[2 * kc][0],     pf_[2 * kc][1]);
            af[1] = packh2(pf_[2 * kc][2],     pf_[2 * kc][3]);
            af[2] = packh2(pf_[2 * kc + 1][0], pf_[2 * kc + 1][1]);
            af[3] = packh2(pf_[2 * kc + 1][2], pf_[2 * kc + 1][3]);
            int kr0 = kc * 16 + 2 * tg;
            #pragma unroll
            for (int nt2 = 0; nt2 < 8; nt2++) {
                int c = nt2 * 8 + g;
                uint32_t bb[2];
                {
                    __half2 hv = __halves2half2(Vs[kr0 * KVH + c], Vs[(kr0 + 1) * KVH + c]);
                    bb[0] = *reinterpret_cast<uint32_t*>(&hv);
                }
                {
                    __half2 hv = __halves2half2(Vs[(kr0 + 8) * KVH + c], Vs[(kr0 + 9) * KVH + c]);
                    bb[1] = *reinterpret_cast<uint32_t*>(&hv);
                }
                mma_f16(o_acc[nt2], af, bb);
            }
        }
        __syncthreads();
    }

    float inv0 = 1.0f / l_r[0], inv1 = 1.0f / l_r[1];
    __half* Og = o + ((size_t)(b * NPp + q0 + w * 16 + g)) * Cc + h * HDd;
    #pragma unroll
    for (int nt2 = 0; nt2 < 8; nt2++) {
        int c = nt2 * 8 + 2 * tg;
        __half2 h0 = __floats2half2_rn(o_acc[nt2][0] * inv0, o_acc[nt2][1] * inv0);
        __half2 h1 = __floats2half2_rn(o_acc[nt2][2] * inv1, o_acc[nt2][3] * inv1);
        *reinterpret_cast<__half2*>(Og + c) = h0;
        *reinterpret_cast<__half2*>(Og + (size_t)8 * Cc + c) = h1;
    }
}

// ---------------- LayerNorm (half output) ----------------
__global__ void ln_kernel(const float* __restrict__ x, const float* __restrict__ g,
                          const float* __restrict__ b, __half* __restrict__ out)
{
    size_t row = blockIdx.x;
    const float* xr = x + row * Cc;
    __half* orow = out + row * Cc;
    int t = threadIdx.x;
    float4 v = reinterpret_cast<const float4*>(xr)[t];
    float s  = v.x + v.y + v.z + v.w;
    float ss = v.x*v.x + v.y*v.y + v.z*v.z + v.w*v.w;
    #pragma unroll
    for (int o = 16; o > 0; o >>= 1) {
        s  += __shfl_xor_sync(0xffffffffu, s,  o);
        ss += __shfl_xor_sync(0xffffffffu, ss, o);
    }
    __shared__ float r0[8], r1[8];
    if ((t & 31) == 0) { r0[t >> 5] = s; r1[t >> 5] = ss; }
    __syncthreads();
    s = 0.f; ss = 0.f;
    #pragma unroll
    for (int i = 0; i < 8; i++) { s += r0[i]; ss += r1[i]; }
    float mu  = s * (1.0f / Cc);
    float var = ss * (1.0f / Cc) - mu * mu;
    float inv = rsqrtf(var + 1e-5f);
    float4 gv = reinterpret_cast<const float4*>(g)[t];
    float4 bv = reinterpret_cast<const float4*>(b)[t];
    __half2 p0 = __floats2half2_rn((v.x - mu) * inv * gv.x + bv.x,
                                   (v.y - mu) * inv * gv.y + bv.y);
    __half2 p1 = __floats2half2_rn((v.z - mu) * inv * gv.z + bv.z,
                                   (v.w - mu) * inv * gv.w + bv.w);
    reinterpret_cast<__half2*>(orow)[2 * t]     = p0;
    reinterpret_cast<__half2*>(orow)[2 * t + 1] = p1;
}

// ---------------- mask scan: warp-parallel prefix scan ----------------
__global__ void p2t_kernel(const unsigned* __restrict__ mask)
{
    int b = blockIdx.x;
    int lane = threadIdx.x;
    const unsigned* mrow = mask + b * Nn;
    int base = lane * 32;
    unsigned bits = 0;
    int cnt = 0;
    #pragma unroll
    for (int i = 0; i < 32; i++) {
        unsigned mv = mrow[base + i] != 0u;
        bits |= mv << i;
        cnt += (int)mv;
    }
    int excl = cnt;
    #pragma unroll
    for (int o = 1; o < 32; o <<= 1) {
        int v = __shfl_up_sync(0xffffffffu, excl, o);
        if (lane >= o) excl += v;
    }
    excl -= cnt;
    int run = excl;
    #pragma unroll
    for (int i = 0; i < 32; i++) {
        bool mv = (bits >> i) & 1u;
        g_p2t[b * Nn + base + i] = mv ? run : -1;
        run += mv ? 1 : 0;
    }
}

// ---------------- KV fill: qkv half gather, cache convert ----------------
__global__ void kvfill_kernel(const float4* __restrict__ ck, const float4* __restrict__ cv)
{
    size_t idx = (size_t)blockIdx.x * blockDim.x + threadIdx.x;   // 4M groups of 4 elems
    int d4 = idx & 15;
    int n  = (idx >> 4) & (Nn - 1);
    int h  = (idx >> 14) & (Hh - 1);
    int b  = (int)(idx >> 18);
    int tok = g_p2t[b * Nn + n];
    uint2 kw, vw;
    if (tok >= 0) {
        const uint2* qkvh = reinterpret_cast<const uint2*>(g_qkv);
        size_t q = ((size_t)(b * NPp + tok)) * (C3 / 4) + (Cc / 4) + h * (HDd / 4) + d4;
        kw = qkvh[q];
        vw = qkvh[q + Cc / 4];
    } else {
        float4 kv = ck[idx];
        float4 vv = cv[idx];
        kw.x = packh2(kv.x, kv.y); kw.y = packh2(kv.z, kv.w);
        vw.x = packh2(vv.x, vv.y); vw.y = packh2(vv.z, vv.w);
    }
    reinterpret_cast<uint2*>(g_kf)[idx] = kw;
    reinterpret_cast<uint2*>(g_vf)[idx] = vw;
}

// ---------------- launch ----------------
extern "C" void kernel_launch(void* const* d_in, const int* in_sizes, int n_in,
                              void* d_out, int out_size)
{
    const float*    x      = (const float*)   d_in[0];
    const float*    cachek = (const float*)   d_in[1];
    const float*    cachev = (const float*)   d_in[2];
    const unsigned* mask   = (const unsigned*)d_in[3];
    const float*    qkv_w  = (const float*)   d_in[4];
    const float*    qkv_b  = (const float*)   d_in[5];
    const float*    proj_w = (const float*)   d_in[6];
    const float*    proj_b = (const float*)   d_in[7];
    const float*    n1_g   = (const float*)   d_in[8];
    const float*    n1_b   = (const float*)   d_in[9];
    const float*    n2_g   = (const float*)   d_in[10];
    const float*    n2_b   = (const float*)   d_in[11];
    const float*    fc1_w  = (const float*)   d_in[12];
    const float*    fc1_b  = (const float*)   d_in[13];
    const float*    fc2_w  = (const float*)   d_in[14];
    const float*    fc2_b  = (const float*)   d_in[15];
    float* out = (float*)d_out;

    __half *h, *o, *hid, *wq, *wp, *w1, *w2, *kf, *vf, *qkv;
    float *x1;
    cudaGetSymbolAddress((void**)&h,   g_h);
    cudaGetSymbolAddress((void**)&qkv, g_qkv);
    cudaGetSymbolAddress((void**)&kf,  g_kf);
    cudaGetSymbolAddress((void**)&vf,  g_vf);
    cudaGetSymbolAddress((void**)&o,   g_o);
    cudaGetSymbolAddress((void**)&x1,  g_x1);
    cudaGetSymbolAddress((void**)&hid, g_hid);
    cudaGetSymbolAddress((void**)&wq,  g_wq);
    cudaGetSymbolAddress((void**)&wp,  g_wp);
    cudaGetSymbolAddress((void**)&w1,  g_w1);
    cudaGetSymbolAddress((void**)&w2,  g_w2);

    const int GEMM_SMEM  = 3 * 9216 * 4;            // 110592 B
    const int FLASH_SMEM = 2 * 2 * 64 * 72 * 2;     // 36864 B
    cudaFuncSetAttribute((const void*)mma_gemm<true, false, false>,
                         cudaFuncAttributeMaxDynamicSharedMemorySize, GEMM_SMEM);
    cudaFuncSetAttribute((const void*)mma_gemm<false, false, true>,
                         cudaFuncAttributeMaxDynamicSharedMemorySize, GEMM_SMEM);
    cudaFuncSetAttribute((const void*)mma_gemm<true, true, false>,
                         cudaFuncAttributeMaxDynamicSharedMemorySize, GEMM_SMEM);
    cudaFuncSetAttribute(flash_kernel,
                         cudaFuncAttributeMaxDynamicSharedMemorySize, FLASH_SMEM);

    // 0. pre-convert + transpose all weights to half [N][K]
    wtrans_kernel<<<12288, 256>>>(qkv_w, proj_w, fc1_w, fc2_w);

    // 1. LN1 -> half
    ln_kernel<<<Mtok, 256>>>(x, n1_g, n1_b, h);

    // 2. QKV = h @ wq^T + qkv_b  (half out)
    mma_gemm<true, false, false><<<dim3(C3 / 128, Mtok / 128), 256, GEMM_SMEM>>>(
        h, wq, qkv, Cc, Cc, Cc, C3, qkv_b, nullptr);

    // 3. mask scan
    p2t_kernel<<<Bb, 32>>>(mask);

    // 4. KV full fill (half)
    kvfill_kernel<<<((Bb * Hh * Nn * HDd) / 4) / 256, 256>>>(
        (const float4*)cachek, (const float4*)cachev);

    // 5-7. fused attention (fp16 mma, half Q)
    flash_kernel<<<dim3(NPp / 128, Bb * Hh), 256, FLASH_SMEM>>>(qkv, kf, vf, o);

    // 8. x1 = x + o @ wp^T + proj_b  (float out)
    mma_gemm<false, false, true><<<dim3(Cc / 128, Mtok / 128), 256, GEMM_SMEM>>>(
        o, wp, x1, Cc, Cc, Cc, Cc, proj_b, x);

    // 9. LN2 -> half
    ln_kernel<<<Mtok, 256>>>(x1, n2_g, n2_b, h);

    // 10. hid = gelu(h @ w1^T + fc1_b)  (half out)
    mma_gemm<true, true, false><<<dim3(HIDh / 128, Mtok / 128), 256, GEMM_SMEM>>>(
        h, w1, hid, Cc, Cc, Cc, HIDh, fc1_b, nullptr);

    // 11. out = x1 + hid @ w2^T + fc2_b  (float out)
    mma_gemm<false, false, true><<<dim3(Cc / 128, Mtok / 128), 256, GEMM_SMEM>>>(
        hid, w2, out, HIDh, HIDh, HIDh, Cc, fc2_b, x1);
}

// round 16
// speedup vs baseline: 1.0320x; 1.0320x over previous
#include <cuda_runtime.h>
#include <cuda_fp16.h>
#include <math.h>
#include <stdint.h>

// Problem constants
#define Bb   16
#define NPp  512
#define Nn   1024
#define Cc   1024
#define Hh   16
#define HDd  64
#define C3   3072
#define HIDh 4096
#define Mtok 8192   // B*NP

// ---------------- scratch (device globals) ----------------
__device__ __half g_h  [(size_t)Mtok * Cc];          // LN out (half)
__device__ __half g_qkv[(size_t)Mtok * C3];          // QKV (half)
__device__ __half g_kf [(size_t)Bb * Hh * Nn * HDd]; // K full (half)
__device__ __half g_vf [(size_t)Bb * Hh * Nn * HDd]; // V full (half)
__device__ __half g_o  [(size_t)Mtok * Cc];          // attention out (half)
__device__ float  g_x1 [(size_t)Mtok * Cc];          // x + proj (float)
__device__ __half g_hid[(size_t)Mtok * HIDh];        // MLP hidden (half)
__device__ int    g_p2t[Bb * Nn];
// half, transposed [N][K] weights
__device__ __half g_wq [(size_t)C3 * Cc];
__device__ __half g_wp [(size_t)Cc * Cc];
__device__ __half g_w1 [(size_t)HIDh * Cc];
__device__ __half g_w2 [(size_t)Cc * HIDh];

// ---------------- helpers ----------------
__device__ __forceinline__ void mma_f16(float c[4], const uint32_t a[4], const uint32_t b[2]) {
    asm volatile(
        "mma.sync.aligned.m16n8k16.row.col.f32.f16.f16.f32 "
        "{%0,%1,%2,%3}, {%4,%5,%6,%7}, {%8,%9}, {%0,%1,%2,%3};"
        : "+f"(c[0]), "+f"(c[1]), "+f"(c[2]), "+f"(c[3])
        : "r"(a[0]), "r"(a[1]), "r"(a[2]), "r"(a[3]), "r"(b[0]), "r"(b[1]));
}
__device__ __forceinline__ uint32_t packh2(float a, float b) {
    __half2 h = __floats2half2_rn(a, b);
    return *reinterpret_cast<uint32_t*>(&h);
}
__device__ __forceinline__ void cp16(uint32_t saddr, const void* g) {
    asm volatile("cp.async.cg.shared.global [%0], [%1], 16;" :: "r"(saddr), "l"(g));
}
#define CP_COMMIT() asm volatile("cp.async.commit_group;")
#define CP_WAIT(n)  asm volatile("cp.async.wait_group %0;" :: "n"(n))

// ---------------- weight pre-round+transpose: float [K][N] -> half [N][K] ----------------
__global__ void wtrans_kernel(const float* __restrict__ wq, const float* __restrict__ wp,
                              const float* __restrict__ w1, const float* __restrict__ w2)
{
    __shared__ __half tile[32][33];
    int bid = blockIdx.x;
    const float* src; __half* dst; int K_, N_, tk, tn;
    if (bid < 3072)      { src = wq; dst = g_wq; K_ = Cc;   N_ = C3;   int id = bid;        tk = id / 96;  tn = id % 96; }
    else if (bid < 4096) { src = wp; dst = g_wp; K_ = Cc;   N_ = Cc;   int id = bid - 3072; tk = id / 32;  tn = id % 32; }
    else if (bid < 8192) { src = w1; dst = g_w1; K_ = Cc;   N_ = HIDh; int id = bid - 4096; tk = id / 128; tn = id % 128; }
    else                 { src = w2; dst = g_w2; K_ = HIDh; N_ = Cc;   int id = bid - 8192; tk = id / 32;  tn = id % 32; }
    int k0 = tk * 32, n0 = tn * 32;
    int t = threadIdx.x;
    #pragma unroll
    for (int it = 0; it < 4; it++) {
        int id = t + it * 256;
        int kk = id >> 5, nn = id & 31;
        tile[kk][nn] = __float2half_rn(src[(size_t)(k0 + kk) * N_ + n0 + nn]);
    }
    __syncthreads();
    #pragma unroll
    for (int it = 0; it < 4; it++) {
        int id = t + it * 256;
        int nn = id >> 5, kk = id & 31;
        dst[(size_t)(n0 + nn) * K_ + k0 + kk] = tile[kk][nn];
    }
}

// ---------------- fp16 mma.sync GEMM, cp.async 3-stage, BK=32 (R13/R14 exact) ----------------
template<bool OUT_HALF, bool GELU_ACT, bool HAS_RES>
__global__ void __launch_bounds__(256) mma_gemm(
    const __half* __restrict__ A, const __half* __restrict__ Bm, void* __restrict__ Cm,
    int K, int lda, int ldb, int ldc,
    const float* __restrict__ bias, const float* __restrict__ resid)
{
    const int AW = 20, BW = 20;
    const int AWORDS = 128 * AW, BWORDS = 128 * BW;
    const int STW = AWORDS + BWORDS;

    extern __shared__ float sm[];

    int t = threadIdx.x, lane = t & 31, warp = t >> 5;
    int g = lane >> 2, tg = lane & 3;
    int wm = (warp >> 2) * 64, wn = (warp & 3) * 32;
    int m0 = blockIdx.y * 128, n0 = blockIdx.x * 128;

    const __half* Ab = A + (size_t)m0 * lda;
    const __half* Bb_ = Bm + (size_t)n0 * ldb;

    float acc[4][4][4];
    #pragma unroll
    for (int i = 0; i < 4; i++)
        #pragma unroll
        for (int j = 0; j < 4; j++)
            #pragma unroll
            for (int l = 0; l < 4; l++) acc[i][j][l] = 0.f;

    auto issue = [&](int kt, int st) {
        float* As = sm + st * STW;
        float* Bs = As + AWORDS;
        const __half* Ag = Ab + kt * 32;
        const __half* Bg = Bb_ + kt * 32;
        #pragma unroll
        for (int it = 0; it < 2; it++) {
            int c = t + it * 256;
            int r = c >> 2, c8 = (c & 3) * 8;
            cp16((uint32_t)__cvta_generic_to_shared(As + r * AW + c8 / 2),
                 Ag + (size_t)r * lda + c8);
        }
        #pragma unroll
        for (int it = 0; it < 2; it++) {
            int c = t + it * 256;
            int r = c >> 2, c8 = (c & 3) * 8;
            cp16((uint32_t)__cvta_generic_to_shared(Bs + r * BW + c8 / 2),
                 Bg + (size_t)r * ldb + c8);
        }
        CP_COMMIT();
    };

    auto compute = [&](int st) {
        const uint32_t* As = reinterpret_cast<const uint32_t*>(sm + st * STW);
        const uint32_t* Bs = As + AWORDS;
        #pragma unroll
        for (int ks = 0; ks < 2; ks++) {
            int k0 = ks * 8;
            uint32_t af[4][4], bf[4][2];
            #pragma unroll
            for (int mt = 0; mt < 4; mt++) {
                int r = wm + mt * 16 + g;
                af[mt][0] = As[r * AW + k0 + tg];
                af[mt][1] = As[(r + 8) * AW + k0 + tg];
                af[mt][2] = As[r * AW + k0 + tg + 4];
                af[mt][3] = As[(r + 8) * AW + k0 + tg + 4];
            }
            #pragma unroll
            for (int nt = 0; nt < 4; nt++) {
                int c = wn + nt * 8 + g;
                bf[nt][0] = Bs[c * BW + k0 + tg];
                bf[nt][1] = Bs[c * BW + k0 + tg + 4];
            }
            #pragma unroll
            for (int mt = 0; mt < 4; mt++)
                #pragma unroll
                for (int nt = 0; nt < 4; nt++)
                    mma_f16(acc[mt][nt], af[mt], bf[nt]);
        }
    };

    const int KT = K / 32;
    issue(0, 0);
    issue(1, 1);

    for (int kt = 0; kt < KT; kt++) {
        if (kt + 1 < KT) { CP_WAIT(1); } else { CP_WAIT(0); }
        __syncthreads();
        compute(kt % 3);
        if (kt + 2 < KT) issue(kt + 2, (kt + 2) % 3);
    }

    #pragma unroll
    for (int mt = 0; mt < 4; mt++) {
        int r0 = m0 + wm + mt * 16 + g;
        #pragma unroll
        for (int nt = 0; nt < 4; nt++) {
            int c = n0 + wn + nt * 8 + 2 * tg;
            #pragma unroll
            for (int half_ = 0; half_ < 2; half_++) {
                int r = r0 + half_ * 8;
                float v0 = acc[mt][nt][half_ * 2 + 0];
                float v1 = acc[mt][nt][half_ * 2 + 1];
                v0 += bias[c]; v1 += bias[c + 1];
                if (GELU_ACT) {
                    v0 = 0.5f * v0 * (1.0f + erff(v0 * 0.70710678118654752f));
                    v1 = 0.5f * v1 * (1.0f + erff(v1 * 0.70710678118654752f));
                }
                if (HAS_RES) {
                    float2 rv = *reinterpret_cast<const float2*>(
                        resid + (size_t)r * ldc + c);
                    v0 += rv.x; v1 += rv.y;
                }
                if (OUT_HALF) {
                    __half2 hv = __floats2half2_rn(v0, v1);
                    *reinterpret_cast<__half2*>((__half*)Cm + (size_t)r * ldc + c) = hv;
                } else {
                    float2 ov; ov.x = v0; ov.y = v1;
                    *reinterpret_cast<float2*>((float*)Cm + (size_t)r * ldc + c) = ov;
                }
            }
        }
    }
}

// ---------------- fused flash attention, fp16 mma, half Q (R15 version) ----------------
__global__ void __launch_bounds__(256) flash_kernel(
    const __half* __restrict__ qkv, const __half* __restrict__ kf,
    const __half* __restrict__ vf, __half* __restrict__ o)
{
    extern __shared__ float fsm[];
    const int KVH = 72;                      // row stride (halves)
    const int KVHALVES = 64 * KVH;

    __half* hsm = reinterpret_cast<__half*>(fsm);

    int t = threadIdx.x, lane = t & 31, w = t >> 5;
    int g = lane >> 2, tg = lane & 3;
    int bh = blockIdx.y, b = bh >> 4, h = bh & 15;
    int q0 = blockIdx.x * 128;

    // ---- Q (half) -> smem ----
    const __half* Qg = qkv + ((size_t)(b * NPp + q0)) * C3 + h * HDd;
    #pragma unroll
    for (int it = 0; it < 4; it++) {
        int id = t + it * 256;               // 1024 chunks of 8 halves
        int r = id >> 3, c8 = (id & 7) * 8;
        uint4 v = *reinterpret_cast<const uint4*>(Qg + (size_t)r * C3 + c8);
        *reinterpret_cast<uint4*>(hsm + r * KVH + c8) = v;
    }
    __syncthreads();

    // ---- Q fragments: scaled by 0.125 via hmul2 ----
    uint32_t qf[4][4];
    {
        const uint32_t* Q32 = reinterpret_cast<const uint32_t*>(hsm);
        const __half2 sc = __floats2half2_rn(0.125f, 0.125f);
        int r0 = w * 16 + g;
        #pragma unroll
        for (int kc = 0; kc < 4; kc++) {
            int wc = kc * 8 + tg;            // word col
            #pragma unroll
            for (int i = 0; i < 4; i++) {
                int rr = (i & 1) ? r0 + 8 : r0;
                int cc = wc + ((i >> 1) ? 4 : 0);
                uint32_t u = Q32[rr * (KVH / 2) + cc];
                __half2 hv = __hmul2(*reinterpret_cast<__half2*>(&u), sc);
                qf[kc][i] = *reinterpret_cast<uint32_t*>(&hv);
            }
        }
    }
    __syncthreads();

    const __half* Kg = kf + (size_t)bh * Nn * HDd;
    const __half* Vg = vf + (size_t)bh * Nn * HDd;

    auto issue_tile = [&](int j, int buf) {
        __half* Ks = hsm + buf * (2 * KVHALVES);
        __half* Vs = Ks + KVHALVES;
        const __half* kg = Kg + (size_t)j * 64 * HDd;
        const __half* vg = Vg + (size_t)j * 64 * HDd;
        #pragma unroll
        for (int it = 0; it < 2; it++) {
            int id = t + it * 256;
            int r = id >> 3, c8 = (id & 7) * 8;
            cp16((uint32_t)__cvta_generic_to_shared(Ks + r * KVH + c8), kg + r * HDd + c8);
            cp16((uint32_t)__cvta_generic_to_shared(Vs + r * KVH + c8), vg + r * HDd + c8);
        }
    };

    float m_r[2] = {-1e30f, -1e30f};
    float l_r[2] = {0.f, 0.f};
    float o_acc[8][4];
    #pragma unroll
    for (int i = 0; i < 8; i++)
        #pragma unroll
        for (int j = 0; j < 4; j++) o_acc[i][j] = 0.f;

    const unsigned FULL = 0xffffffffu;

    issue_tile(0, 0);
    CP_COMMIT();

    for (int j = 0; j < Nn / 64; j++) {
        int buf = j & 1;
        if (j + 1 < Nn / 64) { issue_tile(j + 1, buf ^ 1); CP_COMMIT(); CP_WAIT(1); }
        else                 { CP_WAIT(0); }
        __syncthreads();

        const __half* Ks = hsm + buf * (2 * KVHALVES);
        const __half* Vs = Ks + KVHALVES;
        const uint32_t* K32 = reinterpret_cast<const uint32_t*>(Ks);

        float s[8][4];
        #pragma unroll
        for (int nt = 0; nt < 8; nt++)
            #pragma unroll
            for (int i = 0; i < 4; i++) s[nt][i] = 0.f;
        #pragma unroll
        for (int kc = 0; kc < 4; kc++) {
            #pragma unroll
            for (int nt = 0; nt < 8; nt++) {
                int rowbase = (nt * 8 + g) * (KVH / 2) + kc * 8 + tg;
                uint32_t bb[2];
                bb[0] = K32[rowbase];
                bb[1] = K32[rowbase + 4];
                mma_f16(s[nt], qf[kc], bb);
            }
        }

        float mn0 = m_r[0], mn1 = m_r[1];
        #pragma unroll
        for (int nt = 0; nt < 8; nt++) {
            mn0 = fmaxf(mn0, fmaxf(s[nt][0], s[nt][1]));
            mn1 = fmaxf(mn1, fmaxf(s[nt][2], s[nt][3]));
        }
        mn0 = fmaxf(mn0, __shfl_xor_sync(FULL, mn0, 1));
        mn0 = fmaxf(mn0, __shfl_xor_sync(FULL, mn0, 2));
        mn1 = fmaxf(mn1, __shfl_xor_sync(FULL, mn1, 1));
        mn1 = fmaxf(mn1, __shfl_xor_sync(FULL, mn1, 2));
        float c0 = __expf(m_r[0] - mn0);
        float c1 = __expf(m_r[1] - mn1);
        m_r[0] = mn0; m_r[1] = mn1;

        float pf_[8][4];
        float rs0 = 0.f, rs1 = 0.f;
        #pragma unroll
        for (int nt = 0; nt < 8; nt++) {
            pf_[nt][0] = __expf(s[nt][0] - mn0);
            pf_[nt][1] = __expf(s[nt][1] - mn0);
            pf_[nt][2] = __expf(s[nt][2] - mn1);
            pf_[nt][3] = __expf(s[nt][3] - mn1);
            rs0 += pf_[nt][0] + pf_[nt][1];
            rs1 += pf_[nt][2] + pf_[nt][3];
        }
        rs0 += __shfl_xor_sync(FULL, rs0, 1); rs0 += __shfl_xor_sync(FULL, rs0, 2);
        rs1 += __shfl_xor_sync(FULL, rs1, 1); rs1 += __shfl_xor_sync(FULL, rs1, 2);
        l_r[0] = l_r[0] * c0 + rs0;
        l_r[1] = l_r[1] * c1 + rs1;
        #pragma unroll
        for (int nt = 0; nt < 8; nt++) {
            o_acc[nt][0] *= c0; o_acc[nt][1] *= c0;
            o_acc[nt][2] *= c1; o_acc[nt][3] *= c1;
        }

        #pragma unroll
        for (int kc = 0; kc < 4; kc++) {
            uint32_t af[4];
            af[0] = packh2(pf_[2 * kc][0],     pf_[2 * kc][1]);
            af[1] = packh2(pf_[2 * kc][2],     pf_[2 * kc][3]);
            af[2] = packh2(pf_[2 * kc + 1][0], pf_[2 * kc + 1][1]);
            af[3] = packh2(pf_[2 * kc + 1][2], pf_[2 * kc + 1][3]);
            int kr0 = kc * 16 + 2 * tg;
            #pragma unroll
            for (int nt2 = 0; nt2 < 8; nt2++) {
                int c = nt2 * 8 + g;
                uint32_t bb[2];
                {
                    __half2 hv = __halves2half2(Vs[kr0 * KVH + c], Vs[(kr0 + 1) * KVH + c]);
                    bb[0] = *reinterpret_cast<uint32_t*>(&hv);
                }
                {
                    __half2 hv = __halves2half2(Vs[(kr0 + 8) * KVH + c], Vs[(kr0 + 9) * KVH + c]);
                    bb[1] = *reinterpret_cast<uint32_t*>(&hv);
                }
                mma_f16(o_acc[nt2], af, bb);
            }
        }
        __syncthreads();
    }

    float inv0 = 1.0f / l_r[0], inv1 = 1.0f / l_r[1];
    __half* Og = o + ((size_t)(b * NPp + q0 + w * 16 + g)) * Cc + h * HDd;
    #pragma unroll
    for (int nt2 = 0; nt2 < 8; nt2++) {
        int c = nt2 * 8 + 2 * tg;
        __half2 h0 = __floats2half2_rn(o_acc[nt2][0] * inv0, o_acc[nt2][1] * inv0);
        __half2 h1 = __floats2half2_rn(o_acc[nt2][2] * inv1, o_acc[nt2][3] * inv1);
        *reinterpret_cast<__half2*>(Og + c) = h0;
        *reinterpret_cast<__half2*>(Og + (size_t)8 * Cc + c) = h1;
    }
}

// ---------------- LayerNorm (half output) ----------------
__global__ void ln_kernel(const float* __restrict__ x, const float* __restrict__ g,
                          const float* __restrict__ b, __half* __restrict__ out)
{
    size_t row = blockIdx.x;
    const float* xr = x + row * Cc;
    __half* orow = out + row * Cc;
    int t = threadIdx.x;
    float4 v = reinterpret_cast<const float4*>(xr)[t];
    float s  = v.x + v.y + v.z + v.w;
    float ss = v.x*v.x + v.y*v.y + v.z*v.z + v.w*v.w;
    #pragma unroll
    for (int o = 16; o > 0; o >>= 1) {
        s  += __shfl_xor_sync(0xffffffffu, s,  o);
        ss += __shfl_xor_sync(0xffffffffu, ss, o);
    }
    __shared__ float r0[8], r1[8];
    if ((t & 31) == 0) { r0[t >> 5] = s; r1[t >> 5] = ss; }
    __syncthreads();
    s = 0.f; ss = 0.f;
    #pragma unroll
    for (int i = 0; i < 8; i++) { s += r0[i]; ss += r1[i]; }
    float mu  = s * (1.0f / Cc);
    float var = ss * (1.0f / Cc) - mu * mu;
    float inv = rsqrtf(var + 1e-5f);
    float4 gv = reinterpret_cast<const float4*>(g)[t];
    float4 bv = reinterpret_cast<const float4*>(b)[t];
    __half2 p0 = __floats2half2_rn((v.x - mu) * inv * gv.x + bv.x,
                                   (v.y - mu) * inv * gv.y + bv.y);
    __half2 p1 = __floats2half2_rn((v.z - mu) * inv * gv.z + bv.z,
                                   (v.w - mu) * inv * gv.w + bv.w);
    reinterpret_cast<__half2*>(orow)[2 * t]     = p0;
    reinterpret_cast<__half2*>(orow)[2 * t + 1] = p1;
}

// ---------------- mask scan: warp-parallel prefix scan ----------------
__global__ void p2t_kernel(const unsigned* __restrict__ mask)
{
    int b = blockIdx.x;
    int lane = threadIdx.x;
    const unsigned* mrow = mask + b * Nn;
    int base = lane * 32;
    unsigned bits = 0;
    int cnt = 0;
    #pragma unroll
    for (int i = 0; i < 32; i++) {
        unsigned mv = mrow[base + i] != 0u;
        bits |= mv << i;
        cnt += (int)mv;
    }
    int excl = cnt;
    #pragma unroll
    for (int o = 1; o < 32; o <<= 1) {
        int v = __shfl_up_sync(0xffffffffu, excl, o);
        if (lane >= o) excl += v;
    }
    excl -= cnt;
    int run = excl;
    #pragma unroll
    for (int i = 0; i < 32; i++) {
        bool mv = (bits >> i) & 1u;
        g_p2t[b * Nn + base + i] = mv ? run : -1;
        run += mv ? 1 : 0;
    }
}

// ---------------- KV fill: qkv half gather, cache convert ----------------
__global__ void kvfill_kernel(const float4* __restrict__ ck, const float4* __restrict__ cv)
{
    size_t idx = (size_t)blockIdx.x * blockDim.x + threadIdx.x;   // 4M groups of 4 elems
    int d4 = idx & 15;
    int n  = (idx >> 4) & (Nn - 1);
    int h  = (idx >> 14) & (Hh - 1);
    int b  = (int)(idx >> 18);
    int tok = g_p2t[b * Nn + n];
    uint2 kw, vw;
    if (tok >= 0) {
        const uint2* qkvh = reinterpret_cast<const uint2*>(g_qkv);
        size_t q = ((size_t)(b * NPp + tok)) * (C3 / 4) + (Cc / 4) + h * (HDd / 4) + d4;
        kw = qkvh[q];
        vw = qkvh[q + Cc / 4];
    } else {
        float4 kv = ck[idx];
        float4 vv = cv[idx];
        kw.x = packh2(kv.x, kv.y); kw.y = packh2(kv.z, kv.w);
        vw.x = packh2(vv.x, vv.y); vw.y = packh2(vv.z, vv.w);
    }
    reinterpret_cast<uint2*>(g_kf)[idx] = kw;
    reinterpret_cast<uint2*>(g_vf)[idx] = vw;
}

// ---------------- launch ----------------
extern "C" void kernel_launch(void* const* d_in, const int* in_sizes, int n_in,
                              void* d_out, int out_size)
{
    const float*    x      = (const float*)   d_in[0];
    const float*    cachek = (const float*)   d_in[1];
    const float*    cachev = (const float*)   d_in[2];
    const unsigned* mask   = (const unsigned*)d_in[3];
    const float*    qkv_w  = (const float*)   d_in[4];
    const float*    qkv_b  = (const float*)   d_in[5];
    const float*    proj_w = (const float*)   d_in[6];
    const float*    proj_b = (const float*)   d_in[7];
    const float*    n1_g   = (const float*)   d_in[8];
    const float*    n1_b   = (const float*)   d_in[9];
    const float*    n2_g   = (const float*)   d_in[10];
    const float*    n2_b   = (const float*)   d_in[11];
    const float*    fc1_w  = (const float*)   d_in[12];
    const float*    fc1_b  = (const float*)   d_in[13];
    const float*    fc2_w  = (const float*)   d_in[14];
    const float*    fc2_b  = (const float*)   d_in[15];
    float* out = (float*)d_out;

    __half *h, *o, *hid, *wq, *wp, *w1, *w2, *kf, *vf, *qkv;
    float *x1;
    cudaGetSymbolAddress((void**)&h,   g_h);
    cudaGetSymbolAddress((void**)&qkv, g_qkv);
    cudaGetSymbolAddress((void**)&kf,  g_kf);
    cudaGetSymbolAddress((void**)&vf,  g_vf);
    cudaGetSymbolAddress((void**)&o,   g_o);
    cudaGetSymbolAddress((void**)&x1,  g_x1);
    cudaGetSymbolAddress((void**)&hid, g_hid);
    cudaGetSymbolAddress((void**)&wq,  g_wq);
    cudaGetSymbolAddress((void**)&wp,  g_wp);
    cudaGetSymbolAddress((void**)&w1,  g_w1);
    cudaGetSymbolAddress((void**)&w2,  g_w2);

    const int GEMM_SMEM  = 3 * (128 * 20 + 128 * 20) * 4;   // 61440 B
    const int FLASH_SMEM = 2 * 2 * 64 * 72 * 2;             // 36864 B
    cudaFuncSetAttribute((const void*)mma_gemm<true, false, false>,
                         cudaFuncAttributeMaxDynamicSharedMemorySize, GEMM_SMEM);
    cudaFuncSetAttribute((const void*)mma_gemm<false, false, true>,
                         cudaFuncAttributeMaxDynamicSharedMemorySize, GEMM_SMEM);
    cudaFuncSetAttribute((const void*)mma_gemm<true, true, false>,
                         cudaFuncAttributeMaxDynamicSharedMemorySize, GEMM_SMEM);
    cudaFuncSetAttribute(flash_kernel,
                         cudaFuncAttributeMaxDynamicSharedMemorySize, FLASH_SMEM);

    // 0. pre-convert + transpose all weights to half [N][K]
    wtrans_kernel<<<12288, 256>>>(qkv_w, proj_w, fc1_w, fc2_w);

    // 1. LN1 -> half
    ln_kernel<<<Mtok, 256>>>(x, n1_g, n1_b, h);

    // 2. QKV = h @ wq^T + qkv_b  (half out)
    mma_gemm<true, false, false><<<dim3(C3 / 128, Mtok / 128), 256, GEMM_SMEM>>>(
        h, wq, qkv, Cc, Cc, Cc, C3, qkv_b, nullptr);

    // 3. mask scan
    p2t_kernel<<<Bb, 32>>>(mask);

    // 4. KV full fill (half)
    kvfill_kernel<<<((Bb * Hh * Nn * HDd) / 4) / 256, 256>>>(
        (const float4*)cachek, (const float4*)cachev);

    // 5-7. fused attention (fp16 mma, half Q)
    flash_kernel<<<dim3(NPp / 128, Bb * Hh), 256, FLASH_SMEM>>>(qkv, kf, vf, o);

    // 8. x1 = x + o @ wp^T + proj_b  (float out)
    mma_gemm<false, false, true><<<dim3(Cc / 128, Mtok / 128), 256, GEMM_SMEM>>>(
        o, wp, x1, Cc, Cc, Cc, Cc, proj_b, x);

    // 9. LN2 -> half
    ln_kernel<<<Mtok, 256>>>(x1, n2_g, n2_b, h);

    // 10. hid = gelu(h @ w1^T + fc1_b)  (half out)
    mma_gemm<true, true, false><<<dim3(HIDh / 128, Mtok / 128), 256, GEMM_SMEM>>>(
        h, w1, hid, Cc, Cc, Cc, HIDh, fc1_b, nullptr);

    // 11. out = x1 + hid @ w2^T + fc2_b  (float out)
    mma_gemm<false, false, true><<<dim3(Cc / 128, Mtok / 128), 256, GEMM_SMEM>>>(
        hid, w2, out, HIDh, HIDh, HIDh, Cc, fc2_b, x1);
}

// round 17
// speedup vs baseline: 1.0538x; 1.0212x over previous
#include <cuda_runtime.h>
#include <cuda_fp16.h>
#include <math.h>
#include <stdint.h>

// Problem constants
#define Bb   16
#define NPp  512
#define Nn   1024
#define Cc   1024
#define Hh   16
#define HDd  64
#define C3   3072
#define HIDh 4096
#define Mtok 8192   // B*NP

// ---------------- scratch (device globals) ----------------
__device__ __half g_h  [(size_t)Mtok * Cc];          // LN out (half)
__device__ __half g_qkv[(size_t)Mtok * C3];          // QKV (half)
__device__ __half g_kf [(size_t)Bb * Hh * Nn * HDd]; // K full (half)
__device__ __half g_vf [(size_t)Bb * Hh * Nn * HDd]; // V full (half)
__device__ __half g_o  [(size_t)Mtok * Cc];          // attention out (half)
__device__ float  g_x1 [(size_t)Mtok * Cc];          // x + proj (float)
__device__ __half g_hid[(size_t)Mtok * HIDh];        // MLP hidden (half)
__device__ int    g_p2t[Bb * Nn];
// half, transposed [N][K] weights
__device__ __half g_wq [(size_t)C3 * Cc];
__device__ __half g_wp [(size_t)Cc * Cc];
__device__ __half g_w1 [(size_t)HIDh * Cc];
__device__ __half g_w2 [(size_t)Cc * HIDh];

// ---------------- helpers ----------------
__device__ __forceinline__ void mma_f16(float c[4], const uint32_t a[4], const uint32_t b[2]) {
    asm volatile(
        "mma.sync.aligned.m16n8k16.row.col.f32.f16.f16.f32 "
        "{%0,%1,%2,%3}, {%4,%5,%6,%7}, {%8,%9}, {%0,%1,%2,%3};"
        : "+f"(c[0]), "+f"(c[1]), "+f"(c[2]), "+f"(c[3])
        : "r"(a[0]), "r"(a[1]), "r"(a[2]), "r"(a[3]), "r"(b[0]), "r"(b[1]));
}
__device__ __forceinline__ void ldsm4t(uint32_t r[4], uint32_t a) {
    asm volatile("ldmatrix.sync.aligned.m8n8.x4.trans.shared.b16 {%0,%1,%2,%3}, [%4];"
                 : "=r"(r[0]), "=r"(r[1]), "=r"(r[2]), "=r"(r[3]) : "r"(a));
}
__device__ __forceinline__ uint32_t packh2(float a, float b) {
    __half2 h = __floats2half2_rn(a, b);
    return *reinterpret_cast<uint32_t*>(&h);
}
__device__ __forceinline__ void cp16(uint32_t saddr, const void* g) {
    asm volatile("cp.async.cg.shared.global [%0], [%1], 16;" :: "r"(saddr), "l"(g));
}
#define CP_COMMIT() asm volatile("cp.async.commit_group;")
#define CP_WAIT(n)  asm volatile("cp.async.wait_group %0;" :: "n"(n))

// ---------------- weight pre-round+transpose: float [K][N] -> half [N][K] ----------------
__global__ void wtrans_kernel(const float* __restrict__ wq, const float* __restrict__ wp,
                              const float* __restrict__ w1, const float* __restrict__ w2)
{
    __shared__ __half tile[32][33];
    int bid = blockIdx.x;
    const float* src; __half* dst; int K_, N_, tk, tn;
    if (bid < 3072)      { src = wq; dst = g_wq; K_ = Cc;   N_ = C3;   int id = bid;        tk = id / 96;  tn = id % 96; }
    else if (bid < 4096) { src = wp; dst = g_wp; K_ = Cc;   N_ = Cc;   int id = bid - 3072; tk = id / 32;  tn = id % 32; }
    else if (bid < 8192) { src = w1; dst = g_w1; K_ = Cc;   N_ = HIDh; int id = bid - 4096; tk = id / 128; tn = id % 128; }
    else                 { src = w2; dst = g_w2; K_ = HIDh; N_ = Cc;   int id = bid - 8192; tk = id / 32;  tn = id % 32; }
    int k0 = tk * 32, n0 = tn * 32;
    int t = threadIdx.x;
    #pragma unroll
    for (int it = 0; it < 4; it++) {
        int id = t + it * 256;
        int kk = id >> 5, nn = id & 31;
        tile[kk][nn] = __float2half_rn(src[(size_t)(k0 + kk) * N_ + n0 + nn]);
    }
    __syncthreads();
    #pragma unroll
    for (int it = 0; it < 4; it++) {
        int id = t + it * 256;
        int nn = id >> 5, kk = id & 31;
        dst[(size_t)(n0 + nn) * K_ + k0 + kk] = tile[kk][nn];
    }
}

// ---------------- fp16 mma.sync GEMM, cp.async 3-stage, BK=32 (R13/R14/R16 exact) ----------------
template<bool OUT_HALF, bool GELU_ACT, bool HAS_RES>
__global__ void __launch_bounds__(256) mma_gemm(
    const __half* __restrict__ A, const __half* __restrict__ Bm, void* __restrict__ Cm,
    int K, int lda, int ldb, int ldc,
    const float* __restrict__ bias, const float* __restrict__ resid)
{
    const int AW = 20, BW = 20;
    const int AWORDS = 128 * AW, BWORDS = 128 * BW;
    const int STW = AWORDS + BWORDS;

    extern __shared__ float sm[];

    int t = threadIdx.x, lane = t & 31, warp = t >> 5;
    int g = lane >> 2, tg = lane & 3;
    int wm = (warp >> 2) * 64, wn = (warp & 3) * 32;
    int m0 = blockIdx.y * 128, n0 = blockIdx.x * 128;

    const __half* Ab = A + (size_t)m0 * lda;
    const __half* Bb_ = Bm + (size_t)n0 * ldb;

    float acc[4][4][4];
    #pragma unroll
    for (int i = 0; i < 4; i++)
        #pragma unroll
        for (int j = 0; j < 4; j++)
            #pragma unroll
            for (int l = 0; l < 4; l++) acc[i][j][l] = 0.f;

    auto issue = [&](int kt, int st) {
        float* As = sm + st * STW;
        float* Bs = As + AWORDS;
        const __half* Ag = Ab + kt * 32;
        const __half* Bg = Bb_ + kt * 32;
        #pragma unroll
        for (int it = 0; it < 2; it++) {
            int c = t + it * 256;
            int r = c >> 2, c8 = (c & 3) * 8;
            cp16((uint32_t)__cvta_generic_to_shared(As + r * AW + c8 / 2),
                 Ag + (size_t)r * lda + c8);
        }
        #pragma unroll
        for (int it = 0; it < 2; it++) {
            int c = t + it * 256;
            int r = c >> 2, c8 = (c & 3) * 8;
            cp16((uint32_t)__cvta_generic_to_shared(Bs + r * BW + c8 / 2),
                 Bg + (size_t)r * ldb + c8);
        }
        CP_COMMIT();
    };

    auto compute = [&](int st) {
        const uint32_t* As = reinterpret_cast<const uint32_t*>(sm + st * STW);
        const uint32_t* Bs = As + AWORDS;
        #pragma unroll
        for (int ks = 0; ks < 2; ks++) {
            int k0 = ks * 8;
            uint32_t af[4][4], bf[4][2];
            #pragma unroll
            for (int mt = 0; mt < 4; mt++) {
                int r = wm + mt * 16 + g;
                af[mt][0] = As[r * AW + k0 + tg];
                af[mt][1] = As[(r + 8) * AW + k0 + tg];
                af[mt][2] = As[r * AW + k0 + tg + 4];
                af[mt][3] = As[(r + 8) * AW + k0 + tg + 4];
            }
            #pragma unroll
            for (int nt = 0; nt < 4; nt++) {
                int c = wn + nt * 8 + g;
                bf[nt][0] = Bs[c * BW + k0 + tg];
                bf[nt][1] = Bs[c * BW + k0 + tg + 4];
            }
            #pragma unroll
            for (int mt = 0; mt < 4; mt++)
                #pragma unroll
                for (int nt = 0; nt < 4; nt++)
                    mma_f16(acc[mt][nt], af[mt], bf[nt]);
        }
    };

    const int KT = K / 32;
    issue(0, 0);
    issue(1, 1);

    for (int kt = 0; kt < KT; kt++) {
        if (kt + 1 < KT) { CP_WAIT(1); } else { CP_WAIT(0); }
        __syncthreads();
        compute(kt % 3);
        if (kt + 2 < KT) issue(kt + 2, (kt + 2) % 3);
    }

    #pragma unroll
    for (int mt = 0; mt < 4; mt++) {
        int r0 = m0 + wm + mt * 16 + g;
        #pragma unroll
        for (int nt = 0; nt < 4; nt++) {
            int c = n0 + wn + nt * 8 + 2 * tg;
            #pragma unroll
            for (int half_ = 0; half_ < 2; half_++) {
                int r = r0 + half_ * 8;
                float v0 = acc[mt][nt][half_ * 2 + 0];
                float v1 = acc[mt][nt][half_ * 2 + 1];
                v0 += bias[c]; v1 += bias[c + 1];
                if (GELU_ACT) {
                    v0 = 0.5f * v0 * (1.0f + erff(v0 * 0.70710678118654752f));
                    v1 = 0.5f * v1 * (1.0f + erff(v1 * 0.70710678118654752f));
                }
                if (HAS_RES) {
                    float2 rv = *reinterpret_cast<const float2*>(
                        resid + (size_t)r * ldc + c);
                    v0 += rv.x; v1 += rv.y;
                }
                if (OUT_HALF) {
                    __half2 hv = __floats2half2_rn(v0, v1);
                    *reinterpret_cast<__half2*>((__half*)Cm + (size_t)r * ldc + c) = hv;
                } else {
                    float2 ov; ov.x = v0; ov.y = v1;
                    *reinterpret_cast<float2*>((float*)Cm + (size_t)r * ldc + c) = ov;
                }
            }
        }
    }
}

// ---------------- fused flash attention, fp16 mma, half Q, ldmatrix.trans V ----------------
__global__ void __launch_bounds__(256) flash_kernel(
    const __half* __restrict__ qkv, const __half* __restrict__ kf,
    const __half* __restrict__ vf, __half* __restrict__ o)
{
    extern __shared__ float fsm[];
    const int KVH = 72;                      // row stride (halves)
    const int KVHALVES = 64 * KVH;

    __half* hsm = reinterpret_cast<__half*>(fsm);

    int t = threadIdx.x, lane = t & 31, w = t >> 5;
    int g = lane >> 2, tg = lane & 3;
    int bh = blockIdx.y, b = bh >> 4, h = bh & 15;
    int q0 = blockIdx.x * 128;

    // ---- Q (half) -> smem ----
    const __half* Qg = qkv + ((size_t)(b * NPp + q0)) * C3 + h * HDd;
    #pragma unroll
    for (int it = 0; it < 4; it++) {
        int id = t + it * 256;
        int r = id >> 3, c8 = (id & 7) * 8;
        uint4 v = *reinterpret_cast<const uint4*>(Qg + (size_t)r * C3 + c8);
        *reinterpret_cast<uint4*>(hsm + r * KVH + c8) = v;
    }
    __syncthreads();

    // ---- Q fragments: scaled by 0.125 via hmul2 ----
    uint32_t qf[4][4];
    {
        const uint32_t* Q32 = reinterpret_cast<const uint32_t*>(hsm);
        const __half2 sc = __floats2half2_rn(0.125f, 0.125f);
        int r0 = w * 16 + g;
        #pragma unroll
        for (int kc = 0; kc < 4; kc++) {
            int wc = kc * 8 + tg;
            #pragma unroll
            for (int i = 0; i < 4; i++) {
                int rr = (i & 1) ? r0 + 8 : r0;
                int cc = wc + ((i >> 1) ? 4 : 0);
                uint32_t u = Q32[rr * (KVH / 2) + cc];
                __half2 hv = __hmul2(*reinterpret_cast<__half2*>(&u), sc);
                qf[kc][i] = *reinterpret_cast<uint32_t*>(&hv);
            }
        }
    }
    __syncthreads();

    const __half* Kg = kf + (size_t)bh * Nn * HDd;
    const __half* Vg = vf + (size_t)bh * Nn * HDd;

    auto issue_tile = [&](int j, int buf) {
        __half* Ks = hsm + buf * (2 * KVHALVES);
        __half* Vs = Ks + KVHALVES;
        const __half* kg = Kg + (size_t)j * 64 * HDd;
        const __half* vg = Vg + (size_t)j * 64 * HDd;
        #pragma unroll
        for (int it = 0; it < 2; it++) {
            int id = t + it * 256;
            int r = id >> 3, c8 = (id & 7) * 8;
            cp16((uint32_t)__cvta_generic_to_shared(Ks + r * KVH + c8), kg + r * HDd + c8);
            cp16((uint32_t)__cvta_generic_to_shared(Vs + r * KVH + c8), vg + r * HDd + c8);
        }
    };

    float m_r[2] = {-1e30f, -1e30f};
    float l_r[2] = {0.f, 0.f};
    float o_acc[8][4];
    #pragma unroll
    for (int i = 0; i < 8; i++)
        #pragma unroll
        for (int j = 0; j < 4; j++) o_acc[i][j] = 0.f;

    const unsigned FULL = 0xffffffffu;
    // ldmatrix.trans per-lane offset: matrices 0/1 = k rows 0..15, col group +0;
    // matrices 2/3 = same k rows, col group +8.
    const uint32_t v_lane_off =
        (uint32_t)(((lane & 15) * KVH + ((lane & 16) ? 8 : 0)) * 2);

    issue_tile(0, 0);
    CP_COMMIT();

    for (int j = 0; j < Nn / 64; j++) {
        int buf = j & 1;
        if (j + 1 < Nn / 64) { issue_tile(j + 1, buf ^ 1); CP_COMMIT(); CP_WAIT(1); }
        else                 { CP_WAIT(0); }
        __syncthreads();

        const __half* Ks = hsm + buf * (2 * KVHALVES);
        const __half* Vs = Ks + KVHALVES;
        const uint32_t* K32 = reinterpret_cast<const uint32_t*>(Ks);
        uint32_t vbase = (uint32_t)__cvta_generic_to_shared(Vs) + v_lane_off;

        float s[8][4];
        #pragma unroll
        for (int nt = 0; nt < 8; nt++)
            #pragma unroll
            for (int i = 0; i < 4; i++) s[nt][i] = 0.f;
        #pragma unroll
        for (int kc = 0; kc < 4; kc++) {
            #pragma unroll
            for (int nt = 0; nt < 8; nt++) {
                int rowbase = (nt * 8 + g) * (KVH / 2) + kc * 8 + tg;
                uint32_t bb[2];
                bb[0] = K32[rowbase];
                bb[1] = K32[rowbase + 4];
                mma_f16(s[nt], qf[kc], bb);
            }
        }

        float mn0 = m_r[0], mn1 = m_r[1];
        #pragma unroll
        for (int nt = 0; nt < 8; nt++) {
            mn0 = fmaxf(mn0, fmaxf(s[nt][0], s[nt][1]));
            mn1 = fmaxf(mn1, fmaxf(s[nt][2], s[nt][3]));
        }
        mn0 = fmaxf(mn0, __shfl_xor_sync(FULL, mn0, 1));
        mn0 = fmaxf(mn0, __shfl_xor_sync(FULL, mn0, 2));
        mn1 = fmaxf(mn1, __shfl_xor_sync(FULL, mn1, 1));
        mn1 = fmaxf(mn1, __shfl_xor_sync(FULL, mn1, 2));
        float c0 = __expf(m_r[0] - mn0);
        float c1 = __expf(m_r[1] - mn1);
        m_r[0] = mn0; m_r[1] = mn1;

        float pf_[8][4];
        float rs0 = 0.f, rs1 = 0.f;
        #pragma unroll
        for (int nt = 0; nt < 8; nt++) {
            pf_[nt][0] = __expf(s[nt][0] - mn0);
            pf_[nt][1] = __expf(s[nt][1] - mn0);
            pf_[nt][2] = __expf(s[nt][2] - mn1);
            pf_[nt][3] = __expf(s[nt][3] - mn1);
            rs0 += pf_[nt][0] + pf_[nt][1];
            rs1 += pf_[nt][2] + pf_[nt][3];
        }
        rs0 += __shfl_xor_sync(FULL, rs0, 1); rs0 += __shfl_xor_sync(FULL, rs0, 2);
        rs1 += __shfl_xor_sync(FULL, rs1, 1); rs1 += __shfl_xor_sync(FULL, rs1, 2);
        l_r[0] = l_r[0] * c0 + rs0;
        l_r[1] = l_r[1] * c1 + rs1;
        #pragma unroll
        for (int nt = 0; nt < 8; nt++) {
            o_acc[nt][0] *= c0; o_acc[nt][1] *= c0;
            o_acc[nt][2] *= c1; o_acc[nt][3] *= c1;
        }

        // ---- O += P V : V B-fragments via ldmatrix.x4.trans ----
        #pragma unroll
        for (int kc = 0; kc < 4; kc++) {
            uint32_t af[4];
            af[0] = packh2(pf_[2 * kc][0],     pf_[2 * kc][1]);
            af[1] = packh2(pf_[2 * kc][2],     pf_[2 * kc][3]);
            af[2] = packh2(pf_[2 * kc + 1][0], pf_[2 * kc + 1][1]);
            af[3] = packh2(pf_[2 * kc + 1][2], pf_[2 * kc + 1][3]);
            #pragma unroll
            for (int ntp = 0; ntp < 4; ntp++) {
                uint32_t b4[4];
                ldsm4t(b4, vbase + (uint32_t)((kc * 16 * KVH + ntp * 16) * 2));
                uint32_t bb0[2] = { b4[0], b4[1] };
                mma_f16(o_acc[2 * ntp], af, bb0);
                uint32_t bb1[2] = { b4[2], b4[3] };
                mma_f16(o_acc[2 * ntp + 1], af, bb1);
            }
        }
        __syncthreads();
    }

    float inv0 = 1.0f / l_r[0], inv1 = 1.0f / l_r[1];
    __half* Og = o + ((size_t)(b * NPp + q0 + w * 16 + g)) * Cc + h * HDd;
    #pragma unroll
    for (int nt2 = 0; nt2 < 8; nt2++) {
        int c = nt2 * 8 + 2 * tg;
        __half2 h0 = __floats2half2_rn(o_acc[nt2][0] * inv0, o_acc[nt2][1] * inv0);
        __half2 h1 = __floats2half2_rn(o_acc[nt2][2] * inv1, o_acc[nt2][3] * inv1);
        *reinterpret_cast<__half2*>(Og + c) = h0;
        *reinterpret_cast<__half2*>(Og + (size_t)8 * Cc + c) = h1;
    }
}

// ---------------- LayerNorm (half output) ----------------
__global__ void ln_kernel(const float* __restrict__ x, const float* __restrict__ g,
                          const float* __restrict__ b, __half* __restrict__ out)
{
    size_t row = blockIdx.x;
    const float* xr = x + row * Cc;
    __half* orow = out + row * Cc;
    int t = threadIdx.x;
    float4 v = reinterpret_cast<const float4*>(xr)[t];
    float s  = v.x + v.y + v.z + v.w;
    float ss = v.x*v.x + v.y*v.y + v.z*v.z + v.w*v.w;
    #pragma unroll
    for (int o = 16; o > 0; o >>= 1) {
        s  += __shfl_xor_sync(0xffffffffu, s,  o);
        ss += __shfl_xor_sync(0xffffffffu, ss, o);
    }
    __shared__ float r0[8], r1[8];
    if ((t & 31) == 0) { r0[t >> 5] = s; r1[t >> 5] = ss; }
    __syncthreads();
    s = 0.f; ss = 0.f;
    #pragma unroll
    for (int i = 0; i < 8; i++) { s += r0[i]; ss += r1[i]; }
    float mu  = s * (1.0f / Cc);
    float var = ss * (1.0f / Cc) - mu * mu;
    float inv = rsqrtf(var + 1e-5f);
    float4 gv = reinterpret_cast<const float4*>(g)[t];
    float4 bv = reinterpret_cast<const float4*>(b)[t];
    __half2 p0 = __floats2half2_rn((v.x - mu) * inv * gv.x + bv.x,
                                   (v.y - mu) * inv * gv.y + bv.y);
    __half2 p1 = __floats2half2_rn((v.z - mu) * inv * gv.z + bv.z,
                                   (v.w - mu) * inv * gv.w + bv.w);
    reinterpret_cast<__half2*>(orow)[2 * t]     = p0;
    reinterpret_cast<__half2*>(orow)[2 * t + 1] = p1;
}

// ---------------- mask scan: warp-parallel prefix scan ----------------
__global__ void p2t_kernel(const unsigned* __restrict__ mask)
{
    int b = blockIdx.x;
    int lane = threadIdx.x;
    const unsigned* mrow = mask + b * Nn;
    int base = lane * 32;
    unsigned bits = 0;
    int cnt = 0;
    #pragma unroll
    for (int i = 0; i < 32; i++) {
        unsigned mv = mrow[base + i] != 0u;
        bits |= mv << i;
        cnt += (int)mv;
    }
    int excl = cnt;
    #pragma unroll
    for (int o = 1; o < 32; o <<= 1) {
        int v = __shfl_up_sync(0xffffffffu, excl, o);
        if (lane >= o) excl += v;
    }
    excl -= cnt;
    int run = excl;
    #pragma unroll
    for (int i = 0; i < 32; i++) {
        bool mv = (bits >> i) & 1u;
        g_p2t[b * Nn + base + i] = mv ? run : -1;
        run += mv ? 1 : 0;
    }
}

// ---------------- KV fill: qkv half gather, cache convert ----------------
__global__ void kvfill_kernel(const float4* __restrict__ ck, const float4* __restrict__ cv)
{
    size_t idx = (size_t)blockIdx.x * blockDim.x + threadIdx.x;
    int d4 = idx & 15;
    int n  = (idx >> 4) & (Nn - 1);
    int h  = (idx >> 14) & (Hh - 1);
    int b  = (int)(idx >> 18);
    int tok = g_p2t[b * Nn + n];
    uint2 kw, vw;
    if (tok >= 0) {
        const uint2* qkvh = reinterpret_cast<const uint2*>(g_qkv);
        size_t q = ((size_t)(b * NPp + tok)) * (C3 / 4) + (Cc / 4) + h * (HDd / 4) + d4;
        kw = qkvh[q];
        vw = qkvh[q + Cc / 4];
    } else {
        float4 kv = ck[idx];
        float4 vv = cv[idx];
        kw.x = packh2(kv.x, kv.y); kw.y = packh2(kv.z, kv.w);
        vw.x = packh2(vv.x, vv.y); vw.y = packh2(vv.z, vv.w);
    }
    reinterpret_cast<uint2*>(g_kf)[idx] = kw;
    reinterpret_cast<uint2*>(g_vf)[idx] = vw;
}

// ---------------- launch ----------------
extern "C" void kernel_launch(void* const* d_in, const int* in_sizes, int n_in,
                              void* d_out, int out_size)
{
    const float*    x      = (const float*)   d_in[0];
    const float*    cachek = (const float*)   d_in[1];
    const float*    cachev = (const float*)   d_in[2];
    const unsigned* mask   = (const unsigned*)d_in[3];
    const float*    qkv_w  = (const float*)   d_in[4];
    const float*    qkv_b  = (const float*)   d_in[5];
    const float*    proj_w = (const float*)   d_in[6];
    const float*    proj_b = (const float*)   d_in[7];
    const float*    n1_g   = (const float*)   d_in[8];
    const float*    n1_b   = (const float*)   d_in[9];
    const float*    n2_g   = (const float*)   d_in[10];
    const float*    n2_b   = (const float*)   d_in[11];
    const float*    fc1_w  = (const float*)   d_in[12];
    const float*    fc1_b  = (const float*)   d_in[13];
    const float*    fc2_w  = (const float*)   d_in[14];
    const float*    fc2_b  = (const float*)   d_in[15];
    float* out = (float*)d_out;

    __half *h, *o, *hid, *wq, *wp, *w1, *w2, *kf, *vf, *qkv;
    float *x1;
    cudaGetSymbolAddress((void**)&h,   g_h);
    cudaGetSymbolAddress((void**)&qkv, g_qkv);
    cudaGetSymbolAddress((void**)&kf,  g_kf);
    cudaGetSymbolAddress((void**)&vf,  g_vf);
    cudaGetSymbolAddress((void**)&o,   g_o);
    cudaGetSymbolAddress((void**)&x1,  g_x1);
    cudaGetSymbolAddress((void**)&hid, g_hid);
    cudaGetSymbolAddress((void**)&wq,  g_wq);
    cudaGetSymbolAddress((void**)&wp,  g_wp);
    cudaGetSymbolAddress((void**)&w1,  g_w1);
    cudaGetSymbolAddress((void**)&w2,  g_w2);

    const int GEMM_SMEM  = 3 * (128 * 20 + 128 * 20) * 4;   // 61440 B
    const int FLASH_SMEM = 2 * 2 * 64 * 72 * 2;             // 36864 B
    cudaFuncSetAttribute((const void*)mma_gemm<true, false, false>,
                         cudaFuncAttributeMaxDynamicSharedMemorySize, GEMM_SMEM);
    cudaFuncSetAttribute((const void*)mma_gemm<false, false, true>,
                         cudaFuncAttributeMaxDynamicSharedMemorySize, GEMM_SMEM);
    cudaFuncSetAttribute((const void*)mma_gemm<true, true, false>,
                         cudaFuncAttributeMaxDynamicSharedMemorySize, GEMM_SMEM);
    cudaFuncSetAttribute(flash_kernel,
                         cudaFuncAttributeMaxDynamicSharedMemorySize, FLASH_SMEM);

    // 0. pre-convert + transpose all weights to half [N][K]
    wtrans_kernel<<<12288, 256>>>(qkv_w, proj_w, fc1_w, fc2_w);

    // 1. LN1 -> half
    ln_kernel<<<Mtok, 256>>>(x, n1_g, n1_b, h);

    // 2. QKV = h @ wq^T + qkv_b  (half out)
    mma_gemm<true, false, false><<<dim3(C3 / 128, Mtok / 128), 256, GEMM_SMEM>>>(
        h, wq, qkv, Cc, Cc, Cc, C3, qkv_b, nullptr);

    // 3. mask scan
    p2t_kernel<<<Bb, 32>>>(mask);

    // 4. KV full fill (half)
    kvfill_kernel<<<((Bb * Hh * Nn * HDd) / 4) / 256, 256>>>(
        (const float4*)cachek, (const float4*)cachev);

    // 5-7. fused attention (fp16 mma, half Q, ldmatrix V)
    flash_kernel<<<dim3(NPp / 128, Bb * Hh), 256, FLASH_SMEM>>>(qkv, kf, vf, o);

    // 8. x1 = x + o @ wp^T + proj_b  (float out)
    mma_gemm<false, false, true><<<dim3(Cc / 128, Mtok / 128), 256, GEMM_SMEM>>>(
        o, wp, x1, Cc, Cc, Cc, Cc, proj_b, x);

    // 9. LN2 -> half
    ln_kernel<<<Mtok, 256>>>(x1, n2_g, n2_b, h);

    // 10. hid = gelu(h @ w1^T + fc1_b)  (half out)
    mma_gemm<true, true, false><<<dim3(HIDh / 128, Mtok / 128), 256, GEMM_SMEM>>>(
        h, w1, hid, Cc, Cc, Cc, HIDh, fc1_b, nullptr);

    // 11. out = x1 + hid @ w2^T + fc2_b  (float out)
    mma_gemm<false, false, true><<<dim3(Cc / 128, Mtok / 128), 256, GEMM_SMEM>>>(
        hid, w2, out, HIDh, HIDh, HIDh, Cc, fc2_b, x1);
}